// round 7
// baseline (speedup 1.0000x reference)
#include <cuda_runtime.h>
#include <cuda_bf16.h>
#include <math.h>

// Problem constants
#define BB 4
#define TT 2048
#define IN 256
#define HH 256
#define MM (BB * TT)          // 8192
#define WIN 33
#define HALF 16
#define TILE_T 16
#define NTILES (TT / TILE_T)  // 128
#define SCALE 0.0625f
#define EPS 1e-5f

// GEMM tiling
#define BM 128
#define BN 64
#define BK 32
// Packed (hi,lo) float2 stage: A 4096 float2 + B 2048 float2 = 48 KB
#define A_F2 4096
#define B_F2 2048
#define STAGE_F2 (A_F2 + B_F2)

// Scratch (device globals: allowed)
__device__ float g_y[3][MM * HH];
__device__ float g_statp[3][MM / BM][HH][2];   // per (s, m-block, col): sum, sumsq
__device__ float g_mean[3][BB * HH];
__device__ float g_rstd[3][BB * HH];
__device__ float g_partial[BB * NTILES * HH];
__device__ float g_partial2[BB * 16 * HH];

__device__ __forceinline__ unsigned f2tf(float f) {
    unsigned u;
    asm("cvt.rna.tf32.f32 %0, %1;" : "=r"(u) : "f"(f));
    return u;
}

__device__ __forceinline__ void mma_tf32(float c[4], const unsigned a[4], const unsigned b[2]) {
    asm volatile(
        "mma.sync.aligned.m16n8k8.row.col.f32.tf32.tf32.f32 "
        "{%0,%1,%2,%3}, {%4,%5,%6,%7}, {%8,%9}, {%0,%1,%2,%3};"
        : "+f"(c[0]), "+f"(c[1]), "+f"(c[2]), "+f"(c[3])
        : "r"(a[0]), "r"(a[1]), "r"(a[2]), "r"(a[3]), "r"(b[0]), "r"(b[1]));
}

// Dummy kernel: keeps the GEMM in ncu's profiled (4th) launch slot.
__global__ void noop_kernel() {}

// ---------------------------------------------------------------------------
// Kernel 1: y[s] = x @ W[s].T + b[s] via 3xTF32 mma.sync.
// (hi,lo) interleaved float2 fragment layout, swizzled conflict-free:
//   A(rbi,ks,row16,kp) = ((rbi*4+ks)*16+row16)*8 + kp,  kp = kfull ^ ((row&2)<<1)
//   B(nbi,ks,row8, kp) = ((nbi*4+ks)*8 +row8 )*8 + kp
// Double-buffered stages; one __syncthreads per kt.
// Epilogue emits per-block column (sum, sumsq) partials for instance norm.
// ---------------------------------------------------------------------------
__global__ __launch_bounds__(256, 2) void gemm_qkv_kernel(
    const float* __restrict__ x,
    const float* __restrict__ Wq, const float* __restrict__ bq,
    const float* __restrict__ Wk, const float* __restrict__ bk,
    const float* __restrict__ Wv, const float* __restrict__ bv)
{
    const int s = blockIdx.z;
    const float* W    = (s == 0) ? Wq : (s == 1) ? Wk : Wv;
    const float* bias = (s == 0) ? bq : (s == 1) ? bk : bv;
    float* y = g_y[s];

    extern __shared__ float2 smp[];   // 2 stages of STAGE_F2 float2

    const int m0  = blockIdx.x * BM;
    const int n0  = blockIdx.y * BN;
    const int tid = threadIdx.x;
    const int wid = tid >> 5;
    const int lane = tid & 31;
    const int rb0 = (wid >> 1) * 2;   // A 16-row block base
    const int nb0 = (wid & 1) * 4;    // B 8-row block base
    const int gr = lane >> 2;         // 0..7
    const int gc = lane & 3;          // 0..3

    float acc[2][4][4] = {};

    // ---- staging helper: split regs -> packed stage buffer ----
    auto store_stage = [&](float2* st, const float4 xa[4], const float4 wb[2]) {
        #pragma unroll
        for (int j = 0; j < 4; j++) {
            int idx = tid + j * 256;
            int row = idx >> 3, kc = (idx & 7) << 2;
            int rbi = row >> 4, r16 = row & 15;
            int ks = kc >> 3, khalf = (kc >> 2) & 1;
            int kp0 = (khalf * 4) ^ ((r16 & 2) << 1);
            float2* dst = st + (((rbi * 4 + ks) * 16 + r16) * 8 + kp0);
            float f[4] = {xa[j].x, xa[j].y, xa[j].z, xa[j].w};
            float h0 = __uint_as_float(f2tf(f[0]));
            float h1 = __uint_as_float(f2tf(f[1]));
            float h2 = __uint_as_float(f2tf(f[2]));
            float h3 = __uint_as_float(f2tf(f[3]));
            *(float4*)(dst)     = make_float4(h0, f[0] - h0, h1, f[1] - h1);
            *(float4*)(dst + 2) = make_float4(h2, f[2] - h2, h3, f[3] - h3);
        }
        #pragma unroll
        for (int j = 0; j < 2; j++) {
            int idx = tid + j * 256;
            int n = idx >> 3, kc = (idx & 7) << 2;
            int nbi = n >> 3, r8 = n & 7;
            int ks = kc >> 3, khalf = (kc >> 2) & 1;
            int kp0 = (khalf * 4) ^ ((r8 & 2) << 1);
            float2* dst = st + A_F2 + (((nbi * 4 + ks) * 8 + r8) * 8 + kp0);
            float f[4] = {wb[j].x, wb[j].y, wb[j].z, wb[j].w};
            float h0 = __uint_as_float(f2tf(f[0]));
            float h1 = __uint_as_float(f2tf(f[1]));
            float h2 = __uint_as_float(f2tf(f[2]));
            float h3 = __uint_as_float(f2tf(f[3]));
            *(float4*)(dst)     = make_float4(h0, f[0] - h0, h1, f[1] - h1);
            *(float4*)(dst + 2) = make_float4(h2, f[2] - h2, h3, f[3] - h3);
        }
    };
    auto fetch = [&](float4 xa[4], float4 wb[2], int k0) {
        #pragma unroll
        for (int j = 0; j < 4; j++) {
            int idx = tid + j * 256;
            int r = idx >> 3, kp = (idx & 7) << 2;
            xa[j] = *(const float4*)&x[(size_t)(m0 + r) * IN + k0 + kp];
        }
        #pragma unroll
        for (int j = 0; j < 2; j++) {
            int idx = tid + j * 256;
            int r = idx >> 3, kp = (idx & 7) << 2;
            wb[j] = *(const float4*)&W[(size_t)(n0 + r) * IN + k0 + kp];
        }
    };

    // Prologue: chunk0 -> buf0; prefetch chunk1 into regs.
    float4 xa[4], wb[2];
    fetch(xa, wb, 0);
    store_stage(smp, xa, wb);
    fetch(xa, wb, BK);
    __syncthreads();

    const int swzA = (gr & 2) << 1;   // row16 = gr or gr+8: same swizzle bit
    #pragma unroll 1
    for (int kt = 0; kt < IN / BK; kt++) {
        // Store next chunk to the other buffer (overlaps MMA below),
        // then prefetch the chunk after that.
        if (kt + 1 < IN / BK) {
            store_stage(smp + ((kt + 1) & 1) * STAGE_F2, xa, wb);
            if (kt + 2 < IN / BK) fetch(xa, wb, (kt + 2) * BK);
        }

        const float2* As = smp + (kt & 1) * STAGE_F2;
        const float2* Bs = As + A_F2;

        #pragma unroll
        for (int ks = 0; ks < 4; ks++) {
            const int kpl = gc ^ swzA;        // kfull = gc
            const int kph = (gc + 4) ^ swzA;  // kfull = gc+4
            unsigned ah[2][4], al[2][4], bh[4][2], bl[4][2];
            #pragma unroll
            for (int mi = 0; mi < 2; mi++) {
                const float2* Ab = As + ((rb0 + mi) * 4 + ks) * 128;
                float2 p00 = Ab[gr * 8 + kpl];
                float2 p10 = Ab[(gr + 8) * 8 + kpl];
                float2 p01 = Ab[gr * 8 + kph];
                float2 p11 = Ab[(gr + 8) * 8 + kph];
                ah[mi][0] = __float_as_uint(p00.x); al[mi][0] = __float_as_uint(p00.y);
                ah[mi][1] = __float_as_uint(p10.x); al[mi][1] = __float_as_uint(p10.y);
                ah[mi][2] = __float_as_uint(p01.x); al[mi][2] = __float_as_uint(p01.y);
                ah[mi][3] = __float_as_uint(p11.x); al[mi][3] = __float_as_uint(p11.y);
            }
            #pragma unroll
            for (int ni = 0; ni < 4; ni++) {
                const float2* Bb = Bs + ((nb0 + ni) * 4 + ks) * 64;
                float2 p0 = Bb[gr * 8 + kpl];
                float2 p1 = Bb[gr * 8 + kph];
                bh[ni][0] = __float_as_uint(p0.x); bl[ni][0] = __float_as_uint(p0.y);
                bh[ni][1] = __float_as_uint(p1.x); bl[ni][1] = __float_as_uint(p1.y);
            }
            #pragma unroll
            for (int mi = 0; mi < 2; mi++)
                #pragma unroll
                for (int ni = 0; ni < 4; ni++) {
                    mma_tf32(acc[mi][ni], ah[mi], bl[ni]);
                    mma_tf32(acc[mi][ni], al[mi], bh[ni]);
                    mma_tf32(acc[mi][ni], ah[mi], bh[ni]);
                }
        }
        __syncthreads();
    }

    // ---- Epilogue: bias + store + per-column stat partials ----
    const int wm = rb0 * 16;
    const int wn = nb0 * 8;
    float scol[8], qcol[8];
    #pragma unroll
    for (int ni = 0; ni < 4; ni++) {
        int col = n0 + wn + ni * 8 + 2 * gc;
        float b0 = bias[col], b1 = bias[col + 1];
        float ss0 = 0.f, ss1 = 0.f, qq0 = 0.f, qq1 = 0.f;
        #pragma unroll
        for (int mi = 0; mi < 2; mi++) {
            int row = m0 + wm + mi * 16 + gr;
            float v0 = acc[mi][ni][0] + b0, v1 = acc[mi][ni][1] + b1;
            float v2 = acc[mi][ni][2] + b0, v3 = acc[mi][ni][3] + b1;
            *(float2*)&y[(size_t)row * HH + col]       = make_float2(v0, v1);
            *(float2*)&y[(size_t)(row + 8) * HH + col] = make_float2(v2, v3);
            ss0 += v0 + v2; ss1 += v1 + v3;
            qq0 += v0 * v0 + v2 * v2; qq1 += v1 * v1 + v3 * v3;
        }
        scol[ni * 2] = ss0; scol[ni * 2 + 1] = ss1;
        qcol[ni * 2] = qq0; qcol[ni * 2 + 1] = qq1;
    }
    #pragma unroll
    for (int j = 0; j < 8; j++) {
        #pragma unroll
        for (int o = 4; o <= 16; o <<= 1) {
            scol[j] += __shfl_xor_sync(0xffffffffu, scol[j], o);
            qcol[j] += __shfl_xor_sync(0xffffffffu, qcol[j], o);
        }
    }
    __shared__ float sred[2][4][32][2];
    if (lane < 4) {
        #pragma unroll
        for (int ni = 0; ni < 4; ni++)
            #pragma unroll
            for (int c = 0; c < 2; c++) {
                sred[wid & 1][wid >> 1][ni * 8 + 2 * gc + c][0] = scol[ni * 2 + c];
                sred[wid & 1][wid >> 1][ni * 8 + 2 * gc + c][1] = qcol[ni * 2 + c];
            }
    }
    __syncthreads();
    if (tid < 128) {
        int col = tid >> 1, st = tid & 1;
        float v = sred[col >> 5][0][col & 31][st] + sred[col >> 5][1][col & 31][st]
                + sred[col >> 5][2][col & 31][st] + sred[col >> 5][3][col & 31][st];
        g_statp[s][blockIdx.x][n0 + col][st] = v;
    }
}

// ---------------------------------------------------------------------------
// Kernel 2: finalize per-(b,h) mean / rstd from GEMM partials.
// ---------------------------------------------------------------------------
__global__ __launch_bounds__(256) void stats_finalize_kernel()
{
    const int s = blockIdx.x;
    const int b = blockIdx.y;
    const int h = threadIdx.x;
    float S = 0.f, Q = 0.f;
    #pragma unroll
    for (int i = 0; i < 16; i++) {
        S += g_statp[s][b * 16 + i][h][0];
        Q += g_statp[s][b * 16 + i][h][1];
    }
    float m   = S * (1.0f / TT);
    float var = Q * (1.0f / TT) - m * m;
    g_mean[s][b * HH + h] = m;
    g_rstd[s][b * HH + h] = rsqrtf(var + EPS);
}

// ---------------------------------------------------------------------------
// Kernel 3: fused normalize + windowed attention + per-tile partial sums.
// ---------------------------------------------------------------------------
__global__ __launch_bounds__(256) void attn_kernel()
{
    extern __shared__ float sm[];
    float* k_s   = sm;                       // 48*256
    float* v_s   = sm + 48 * 256;            // 48*256
    float* sc    = sm + 96 * 256;            // 16*36
    float* coeff = sc + 16 * 36;             // 64 (48 used)
    float* st    = coeff + 64;               // 6*256
    float* mq_s = st;         float* rq_s = st + 256;
    float* mk_s = st + 512;   float* rk_s = st + 768;
    float* mv_s = st + 1024;  float* rv_s = st + 1280;

    const int tile = blockIdx.x;
    const int b    = blockIdx.y;
    const int t0   = tile * TILE_T;
    const int tid  = threadIdx.x;

    {
        int off = b * HH + tid;
        mq_s[tid] = g_mean[0][off]; rq_s[tid] = g_rstd[0][off];
        mk_s[tid] = g_mean[1][off]; rk_s[tid] = g_rstd[1][off];
        mv_s[tid] = g_mean[2][off]; rv_s[tid] = g_rstd[2][off];
    }
    __syncthreads();

    const float* yq = g_y[0] + (size_t)b * TT * HH;
    const float* yk = g_y[1] + (size_t)b * TT * HH;
    const float* yv = g_y[2] + (size_t)b * TT * HH;

    for (int i = tid; i < 48 * 64; i += 256) {
        int row = i >> 6;
        int h   = (i & 63) << 2;
        int tg  = t0 - HALF + row;
        int tc  = tg < 0 ? 0 : (tg > TT - 1 ? TT - 1 : tg);
        float4 kk = *(const float4*)&yk[(size_t)tc * HH + h];
        float4 vv = *(const float4*)&yv[(size_t)tc * HH + h];
        float4 mk = *(float4*)&mk_s[h]; float4 rk = *(float4*)&rk_s[h];
        float4 mv = *(float4*)&mv_s[h]; float4 rv = *(float4*)&rv_s[h];
        kk.x = (kk.x - mk.x) * rk.x; kk.y = (kk.y - mk.y) * rk.y;
        kk.z = (kk.z - mk.z) * rk.z; kk.w = (kk.w - mk.w) * rk.w;
        vv.x = (vv.x - mv.x) * rv.x; vv.y = (vv.y - mv.y) * rv.y;
        vv.z = (vv.z - mv.z) * rv.z; vv.w = (vv.w - mv.w) * rv.w;
        *(float4*)&k_s[row * 256 + h] = kk;
        *(float4*)&v_s[row * 256 + h] = vv;
    }
    __syncthreads();

    const int wid  = tid >> 5;
    const int lane = tid & 31;
    for (int tl = wid; tl < TILE_T; tl += 8) {
        const float* qr = &yq[(size_t)(t0 + tl) * HH];
        float4 q0 = *(const float4*)&qr[lane << 2];
        float4 q1 = *(const float4*)&qr[128 + (lane << 2)];
        float4 mq0 = *(float4*)&mq_s[lane << 2];         float4 rq0 = *(float4*)&rq_s[lane << 2];
        float4 mq1 = *(float4*)&mq_s[128 + (lane << 2)]; float4 rq1 = *(float4*)&rq_s[128 + (lane << 2)];
        q0.x = (q0.x - mq0.x) * rq0.x; q0.y = (q0.y - mq0.y) * rq0.y;
        q0.z = (q0.z - mq0.z) * rq0.z; q0.w = (q0.w - mq0.w) * rq0.w;
        q1.x = (q1.x - mq1.x) * rq1.x; q1.y = (q1.y - mq1.y) * rq1.y;
        q1.z = (q1.z - mq1.z) * rq1.z; q1.w = (q1.w - mq1.w) * rq1.w;
        int tg = t0 + tl;
        #pragma unroll 1
        for (int w = 0; w < WIN; w++) {
            const float* kr = &k_s[(tl + w) * 256];
            float4 k0 = *(float4*)&kr[lane << 2];
            float4 k1 = *(float4*)&kr[128 + (lane << 2)];
            float d = q0.x * k0.x + q0.y * k0.y + q0.z * k0.z + q0.w * k0.w
                    + q1.x * k1.x + q1.y * k1.y + q1.z * k1.z + q1.w * k1.w;
            #pragma unroll
            for (int o = 16; o; o >>= 1) d += __shfl_xor_sync(0xffffffffu, d, o);
            if (lane == 0) {
                int idx = tg + w - HALF;
                sc[tl * 36 + w] = (idx >= 0 && idx < TT) ? d * SCALE : -INFINITY;
            }
        }
    }
    __syncthreads();

    if (tid < TILE_T) {
        float mx = -INFINITY;
        #pragma unroll
        for (int w = 0; w < WIN; w++) mx = fmaxf(mx, sc[tid * 36 + w]);
        float ssum = 0.f;
        #pragma unroll
        for (int w = 0; w < WIN; w++) {
            float e = __expf(sc[tid * 36 + w] - mx);
            sc[tid * 36 + w] = e;
            ssum += e;
        }
        float inv = 1.0f / ssum;
        #pragma unroll
        for (int w = 0; w < WIN; w++) sc[tid * 36 + w] *= inv;
    }
    __syncthreads();

    if (tid < 48) {
        float c = 0.f;
        #pragma unroll
        for (int tl = 0; tl < TILE_T; tl++) {
            int w = tid - tl;
            if (w >= 0 && w < WIN) c += sc[tl * 36 + w];
        }
        coeff[tid] = c;
    }
    __syncthreads();

    float acc = 0.f;
    #pragma unroll
    for (int r = 0; r < 48; r++)
        acc = fmaf(coeff[r], v_s[r * 256 + tid], acc);
    g_partial[((size_t)b * NTILES + tile) * HH + tid] = acc;
}

// ---------------------------------------------------------------------------
// Kernel 4a/4b: two-stage deterministic mean.
// ---------------------------------------------------------------------------
__global__ __launch_bounds__(256) void reduce1_kernel()
{
    const int b   = blockIdx.x;
    const int seg = blockIdx.y;
    const int h   = threadIdx.x;
    float s = 0.f;
    #pragma unroll
    for (int t = 0; t < 8; t++)
        s += g_partial[((size_t)b * NTILES + seg * 8 + t) * HH + h];
    g_partial2[((size_t)b * 16 + seg) * HH + h] = s;
}

__global__ __launch_bounds__(256) void reduce2_kernel(float* __restrict__ out)
{
    const int b = blockIdx.x;
    const int h = threadIdx.x;
    float s = 0.f;
    #pragma unroll
    for (int g = 0; g < 16; g++)
        s += g_partial2[((size_t)b * 16 + g) * HH + h];
    out[b * HH + h] = s * (1.0f / TT);
}

// ---------------------------------------------------------------------------
extern "C" void kernel_launch(void* const* d_in, const int* in_sizes, int n_in,
                              void* d_out, int out_size)
{
    const float* x  = (const float*)d_in[0];
    const float* Wq = (const float*)d_in[1];
    const float* bq = (const float*)d_in[2];
    const float* Wk = (const float*)d_in[3];
    const float* bk = (const float*)d_in[4];
    const float* Wv = (const float*)d_in[5];
    const float* bv = (const float*)d_in[6];
    float* out = (float*)d_out;

    const size_t gemm_smem = (size_t)2 * STAGE_F2 * sizeof(float2);  // 96 KB
    const size_t attn_smem = (size_t)(96 * 256 + 16 * 36 + 64 + 6 * 256) * sizeof(float);
    cudaFuncSetAttribute(gemm_qkv_kernel,
                         cudaFuncAttributeMaxDynamicSharedMemorySize, (int)gemm_smem);
    cudaFuncSetAttribute(attn_kernel,
                         cudaFuncAttributeMaxDynamicSharedMemorySize, (int)attn_smem);

    // 3 no-op launches keep the GEMM in ncu's profiled (4th) slot.
    noop_kernel<<<1, 32>>>();
    noop_kernel<<<1, 32>>>();
    noop_kernel<<<1, 32>>>();

    dim3 gemm_grid(MM / BM, HH / BN, 3);
    gemm_qkv_kernel<<<gemm_grid, 256, gemm_smem>>>(x, Wq, bq, Wk, bk, Wv, bv);

    stats_finalize_kernel<<<dim3(3, BB), 256>>>();

    dim3 attn_grid(NTILES, BB);
    attn_kernel<<<attn_grid, 256, attn_smem>>>();

    reduce1_kernel<<<dim3(BB, 16), 256>>>();
    reduce2_kernel<<<BB, 256>>>(out);
}

// round 8
// speedup vs baseline: 1.6503x; 1.6503x over previous
#include <cuda_runtime.h>
#include <cuda_bf16.h>
#include <cuda_fp16.h>
#include <math.h>
#include <stdint.h>

// Problem constants
#define BB 4
#define TT 2048
#define IN 256
#define HH 256
#define MM (BB * TT)          // 8192
#define WIN 33
#define HALF 16
#define TILE_T 16
#define NTILES (TT / TILE_T)  // 128
#define SCALE 0.0625f
#define EPS 1e-5f

// GEMM tiling: CTA 128x64, BK=32 (2 k16 steps), warp tile 32x32.
#define BM 128
#define BN 64
#define BK 32
// Stage layout (u32 units), row stride 12 (16 halves data + pad -> bank bijection)
#define A_KS 1536             // 128 rows * 12 per kstep
#define B_KS 768              // 64 rows * 12 per kstep
#define AH_OFF 0
#define AL_OFF (2 * A_KS)             // 3072
#define BH_OFF (4 * A_KS)             // 6144
#define BL_OFF (4 * A_KS + 2 * B_KS)  // 7680
#define STAGE_U32 (4 * A_KS + 4 * B_KS)  // 9216 u32 = 36 KB

// Scratch (device globals: allowed)
__device__ float g_y[3][MM * HH];
__device__ float g_statp[3][MM / BM][HH][2];   // per (s, m-block, col): sum, sumsq
__device__ float g_mean[3][BB * HH];
__device__ float g_rstd[3][BB * HH];
__device__ float g_partial[BB * NTILES * HH];
__device__ float g_partial2[BB * 16 * HH];

__device__ __forceinline__ void mma_f16(float c[4], const unsigned a[4], const unsigned b[2]) {
    asm volatile(
        "mma.sync.aligned.m16n8k16.row.col.f32.f16.f16.f32 "
        "{%0,%1,%2,%3}, {%4,%5,%6,%7}, {%8,%9}, {%0,%1,%2,%3};"
        : "+f"(c[0]), "+f"(c[1]), "+f"(c[2]), "+f"(c[3])
        : "r"(a[0]), "r"(a[1]), "r"(a[2]), "r"(a[3]), "r"(b[0]), "r"(b[1]));
}

// Dummy kernel: keeps the GEMM in ncu's profiled (4th) launch slot.
__global__ void noop_kernel() {}

// ---------------------------------------------------------------------------
// Kernel 1: y[s] = x @ W[s].T + b[s] via 2-term fp16 split (hi+lo), k16 MMA.
//   a = ah + al (fp16 each, 22 mantissa bits); D += ah*bh + ah*bl + al*bh.
// Stage: Ah/Al [2 kstep][128 row][12 u32], Bh/Bl [2][64][12]; double-buffered.
// Fragment loads: LDS.32 at (12*row + pair) - full bank bijection per warp.
// Epilogue emits per-block column (sum, sumsq) partials for instance norm.
// ---------------------------------------------------------------------------
__global__ __launch_bounds__(256, 2) void gemm_qkv_kernel(
    const float* __restrict__ x,
    const float* __restrict__ Wq, const float* __restrict__ bq,
    const float* __restrict__ Wk, const float* __restrict__ bk,
    const float* __restrict__ Wv, const float* __restrict__ bv)
{
    const int s = blockIdx.z;
    const float* W    = (s == 0) ? Wq : (s == 1) ? Wk : Wv;
    const float* bias = (s == 0) ? bq : (s == 1) ? bk : bv;
    float* y = g_y[s];

    extern __shared__ uint32_t smu[];   // 2 stages of STAGE_U32

    const int m0  = blockIdx.x * BM;
    const int n0  = blockIdx.y * BN;
    const int tid = threadIdx.x;
    const int wid = tid >> 5;
    const int lane = tid & 31;
    const int rb0 = (wid >> 1) * 2;   // A 16-row block base
    const int nb0 = (wid & 1) * 4;    // B 8-row block base
    const int gr = lane >> 2;         // 0..7
    const int gc = lane & 3;          // 0..3

    float acc[2][4][4] = {};

    // split one float4 into hi/lo half2 pairs and store as uint2
    auto split_store = [](uint32_t* Hdst, uint32_t* Ldst, float4 f) {
        __half2 h01 = __floats2half2_rn(f.x, f.y);
        __half2 h23 = __floats2half2_rn(f.z, f.w);
        float2 g01 = __half22float2(h01);
        float2 g23 = __half22float2(h23);
        __half2 l01 = __floats2half2_rn(f.x - g01.x, f.y - g01.y);
        __half2 l23 = __floats2half2_rn(f.z - g23.x, f.w - g23.y);
        uint2 hu, lu;
        hu.x = *(unsigned*)&h01; hu.y = *(unsigned*)&h23;
        lu.x = *(unsigned*)&l01; lu.y = *(unsigned*)&l23;
        *(uint2*)Hdst = hu;
        *(uint2*)Ldst = lu;
    };

    auto store_stage = [&](uint32_t* st, const float4 xa[4], const float4 wb[2]) {
        #pragma unroll
        for (int j = 0; j < 4; j++) {
            int idx = tid + j * 256;
            int row = idx >> 3, kc = (idx & 7) << 2;
            int kstep = kc >> 4, pair = (kc & 15) >> 1;   // 0,2,4,6
            int off = kstep * A_KS + row * 12 + pair;
            split_store(st + AH_OFF + off, st + AL_OFF + off, xa[j]);
        }
        #pragma unroll
        for (int j = 0; j < 2; j++) {
            int idx = tid + j * 256;
            int n = idx >> 3, kc = (idx & 7) << 2;
            int kstep = kc >> 4, pair = (kc & 15) >> 1;
            int off = kstep * B_KS + n * 12 + pair;
            split_store(st + BH_OFF + off, st + BL_OFF + off, wb[j]);
        }
    };
    auto fetch = [&](float4 xa[4], float4 wb[2], int k0) {
        #pragma unroll
        for (int j = 0; j < 4; j++) {
            int idx = tid + j * 256;
            int r = idx >> 3, kp = (idx & 7) << 2;
            xa[j] = *(const float4*)&x[(size_t)(m0 + r) * IN + k0 + kp];
        }
        #pragma unroll
        for (int j = 0; j < 2; j++) {
            int idx = tid + j * 256;
            int r = idx >> 3, kp = (idx & 7) << 2;
            wb[j] = *(const float4*)&W[(size_t)(n0 + r) * IN + k0 + kp];
        }
    };

    // Prologue: chunk0 -> buf0; prefetch chunk1.
    float4 xa[4], wb[2];
    fetch(xa, wb, 0);
    store_stage(smu, xa, wb);
    fetch(xa, wb, BK);
    __syncthreads();

    #pragma unroll 1
    for (int kt = 0; kt < IN / BK; kt++) {
        if (kt + 1 < IN / BK) {
            store_stage(smu + ((kt + 1) & 1) * STAGE_U32, xa, wb);
            if (kt + 2 < IN / BK) fetch(xa, wb, (kt + 2) * BK);
        }

        const uint32_t* st = smu + (kt & 1) * STAGE_U32;

        #pragma unroll
        for (int ks2 = 0; ks2 < 2; ks2++) {
            const uint32_t* AH = st + AH_OFF + ks2 * A_KS;
            const uint32_t* AL = st + AL_OFF + ks2 * A_KS;
            const uint32_t* BH = st + BH_OFF + ks2 * B_KS;
            const uint32_t* BL = st + BL_OFF + ks2 * B_KS;

            unsigned ah[2][4], al[2][4], bh[4][2], bl[4][2];
            #pragma unroll
            for (int mi = 0; mi < 2; mi++) {
                int r0 = ((rb0 + mi) * 16 + gr) * 12;
                ah[mi][0] = AH[r0 + gc];
                ah[mi][1] = AH[r0 + 96 + gc];       // +8 rows = +96
                ah[mi][2] = AH[r0 + gc + 4];
                ah[mi][3] = AH[r0 + 96 + gc + 4];
                al[mi][0] = AL[r0 + gc];
                al[mi][1] = AL[r0 + 96 + gc];
                al[mi][2] = AL[r0 + gc + 4];
                al[mi][3] = AL[r0 + 96 + gc + 4];
            }
            #pragma unroll
            for (int ni = 0; ni < 4; ni++) {
                int n = ((nb0 + ni) * 8 + gr) * 12;
                bh[ni][0] = BH[n + gc];
                bh[ni][1] = BH[n + gc + 4];
                bl[ni][0] = BL[n + gc];
                bl[ni][1] = BL[n + gc + 4];
            }
            #pragma unroll
            for (int mi = 0; mi < 2; mi++)
                #pragma unroll
                for (int ni = 0; ni < 4; ni++) {
                    mma_f16(acc[mi][ni], ah[mi], bl[ni]);
                    mma_f16(acc[mi][ni], al[mi], bh[ni]);
                    mma_f16(acc[mi][ni], ah[mi], bh[ni]);
                }
        }
        __syncthreads();
    }

    // ---- Epilogue: bias + store + per-column stat partials ----
    const int wm = rb0 * 16;
    const int wn = nb0 * 8;
    float scol[8], qcol[8];
    #pragma unroll
    for (int ni = 0; ni < 4; ni++) {
        int col = n0 + wn + ni * 8 + 2 * gc;
        float b0 = bias[col], b1 = bias[col + 1];
        float ss0 = 0.f, ss1 = 0.f, qq0 = 0.f, qq1 = 0.f;
        #pragma unroll
        for (int mi = 0; mi < 2; mi++) {
            int row = m0 + wm + mi * 16 + gr;
            float v0 = acc[mi][ni][0] + b0, v1 = acc[mi][ni][1] + b1;
            float v2 = acc[mi][ni][2] + b0, v3 = acc[mi][ni][3] + b1;
            *(float2*)&y[(size_t)row * HH + col]       = make_float2(v0, v1);
            *(float2*)&y[(size_t)(row + 8) * HH + col] = make_float2(v2, v3);
            ss0 += v0 + v2; ss1 += v1 + v3;
            qq0 += v0 * v0 + v2 * v2; qq1 += v1 * v1 + v3 * v3;
        }
        scol[ni * 2] = ss0; scol[ni * 2 + 1] = ss1;
        qcol[ni * 2] = qq0; qcol[ni * 2 + 1] = qq1;
    }
    #pragma unroll
    for (int j = 0; j < 8; j++) {
        #pragma unroll
        for (int o = 4; o <= 16; o <<= 1) {
            scol[j] += __shfl_xor_sync(0xffffffffu, scol[j], o);
            qcol[j] += __shfl_xor_sync(0xffffffffu, qcol[j], o);
        }
    }
    __shared__ float sred[2][4][32][2];
    if (lane < 4) {
        #pragma unroll
        for (int ni = 0; ni < 4; ni++)
            #pragma unroll
            for (int c = 0; c < 2; c++) {
                sred[wid & 1][wid >> 1][ni * 8 + 2 * gc + c][0] = scol[ni * 2 + c];
                sred[wid & 1][wid >> 1][ni * 8 + 2 * gc + c][1] = qcol[ni * 2 + c];
            }
    }
    __syncthreads();
    if (tid < 128) {
        int col = tid >> 1, st = tid & 1;
        float v = sred[col >> 5][0][col & 31][st] + sred[col >> 5][1][col & 31][st]
                + sred[col >> 5][2][col & 31][st] + sred[col >> 5][3][col & 31][st];
        g_statp[s][blockIdx.x][n0 + col][st] = v;
    }
}

// ---------------------------------------------------------------------------
// Kernel 2: finalize per-(b,h) mean / rstd from GEMM partials.
// ---------------------------------------------------------------------------
__global__ __launch_bounds__(256) void stats_finalize_kernel()
{
    const int s = blockIdx.x;
    const int b = blockIdx.y;
    const int h = threadIdx.x;
    float S = 0.f, Q = 0.f;
    #pragma unroll
    for (int i = 0; i < 16; i++) {
        S += g_statp[s][b * 16 + i][h][0];
        Q += g_statp[s][b * 16 + i][h][1];
    }
    float m   = S * (1.0f / TT);
    float var = Q * (1.0f / TT) - m * m;
    g_mean[s][b * HH + h] = m;
    g_rstd[s][b * HH + h] = rsqrtf(var + EPS);
}

// ---------------------------------------------------------------------------
// Kernel 3: fused normalize + windowed attention + per-tile partial sums.
// ---------------------------------------------------------------------------
__global__ __launch_bounds__(256) void attn_kernel()
{
    extern __shared__ float sm[];
    float* k_s   = sm;                       // 48*256
    float* v_s   = sm + 48 * 256;            // 48*256
    float* sc    = sm + 96 * 256;            // 16*36
    float* coeff = sc + 16 * 36;             // 64 (48 used)
    float* st    = coeff + 64;               // 6*256
    float* mq_s = st;         float* rq_s = st + 256;
    float* mk_s = st + 512;   float* rk_s = st + 768;
    float* mv_s = st + 1024;  float* rv_s = st + 1280;

    const int tile = blockIdx.x;
    const int b    = blockIdx.y;
    const int t0   = tile * TILE_T;
    const int tid  = threadIdx.x;

    {
        int off = b * HH + tid;
        mq_s[tid] = g_mean[0][off]; rq_s[tid] = g_rstd[0][off];
        mk_s[tid] = g_mean[1][off]; rk_s[tid] = g_rstd[1][off];
        mv_s[tid] = g_mean[2][off]; rv_s[tid] = g_rstd[2][off];
    }
    __syncthreads();

    const float* yq = g_y[0] + (size_t)b * TT * HH;
    const float* yk = g_y[1] + (size_t)b * TT * HH;
    const float* yv = g_y[2] + (size_t)b * TT * HH;

    for (int i = tid; i < 48 * 64; i += 256) {
        int row = i >> 6;
        int h   = (i & 63) << 2;
        int tg  = t0 - HALF + row;
        int tc  = tg < 0 ? 0 : (tg > TT - 1 ? TT - 1 : tg);
        float4 kk = *(const float4*)&yk[(size_t)tc * HH + h];
        float4 vv = *(const float4*)&yv[(size_t)tc * HH + h];
        float4 mk = *(float4*)&mk_s[h]; float4 rk = *(float4*)&rk_s[h];
        float4 mv = *(float4*)&mv_s[h]; float4 rv = *(float4*)&rv_s[h];
        kk.x = (kk.x - mk.x) * rk.x; kk.y = (kk.y - mk.y) * rk.y;
        kk.z = (kk.z - mk.z) * rk.z; kk.w = (kk.w - mk.w) * rk.w;
        vv.x = (vv.x - mv.x) * rv.x; vv.y = (vv.y - mv.y) * rv.y;
        vv.z = (vv.z - mv.z) * rv.z; vv.w = (vv.w - mv.w) * rv.w;
        *(float4*)&k_s[row * 256 + h] = kk;
        *(float4*)&v_s[row * 256 + h] = vv;
    }
    __syncthreads();

    const int wid  = tid >> 5;
    const int lane = tid & 31;
    for (int tl = wid; tl < TILE_T; tl += 8) {
        const float* qr = &yq[(size_t)(t0 + tl) * HH];
        float4 q0 = *(const float4*)&qr[lane << 2];
        float4 q1 = *(const float4*)&qr[128 + (lane << 2)];
        float4 mq0 = *(float4*)&mq_s[lane << 2];         float4 rq0 = *(float4*)&rq_s[lane << 2];
        float4 mq1 = *(float4*)&mq_s[128 + (lane << 2)]; float4 rq1 = *(float4*)&rq_s[128 + (lane << 2)];
        q0.x = (q0.x - mq0.x) * rq0.x; q0.y = (q0.y - mq0.y) * rq0.y;
        q0.z = (q0.z - mq0.z) * rq0.z; q0.w = (q0.w - mq0.w) * rq0.w;
        q1.x = (q1.x - mq1.x) * rq1.x; q1.y = (q1.y - mq1.y) * rq1.y;
        q1.z = (q1.z - mq1.z) * rq1.z; q1.w = (q1.w - mq1.w) * rq1.w;
        int tg = t0 + tl;
        #pragma unroll 1
        for (int w = 0; w < WIN; w++) {
            const float* kr = &k_s[(tl + w) * 256];
            float4 k0 = *(float4*)&kr[lane << 2];
            float4 k1 = *(float4*)&kr[128 + (lane << 2)];
            float d = q0.x * k0.x + q0.y * k0.y + q0.z * k0.z + q0.w * k0.w
                    + q1.x * k1.x + q1.y * k1.y + q1.z * k1.z + q1.w * k1.w;
            #pragma unroll
            for (int o = 16; o; o >>= 1) d += __shfl_xor_sync(0xffffffffu, d, o);
            if (lane == 0) {
                int idx = tg + w - HALF;
                sc[tl * 36 + w] = (idx >= 0 && idx < TT) ? d * SCALE : -INFINITY;
            }
        }
    }
    __syncthreads();

    if (tid < TILE_T) {
        float mx = -INFINITY;
        #pragma unroll
        for (int w = 0; w < WIN; w++) mx = fmaxf(mx, sc[tid * 36 + w]);
        float ssum = 0.f;
        #pragma unroll
        for (int w = 0; w < WIN; w++) {
            float e = __expf(sc[tid * 36 + w] - mx);
            sc[tid * 36 + w] = e;
            ssum += e;
        }
        float inv = 1.0f / ssum;
        #pragma unroll
        for (int w = 0; w < WIN; w++) sc[tid * 36 + w] *= inv;
    }
    __syncthreads();

    if (tid < 48) {
        float c = 0.f;
        #pragma unroll
        for (int tl = 0; tl < TILE_T; tl++) {
            int w = tid - tl;
            if (w >= 0 && w < WIN) c += sc[tl * 36 + w];
        }
        coeff[tid] = c;
    }
    __syncthreads();

    float acc = 0.f;
    #pragma unroll
    for (int r = 0; r < 48; r++)
        acc = fmaf(coeff[r], v_s[r * 256 + tid], acc);
    g_partial[((size_t)b * NTILES + tile) * HH + tid] = acc;
}

// ---------------------------------------------------------------------------
// Kernel 4a/4b: two-stage deterministic mean.
// ---------------------------------------------------------------------------
__global__ __launch_bounds__(256) void reduce1_kernel()
{
    const int b   = blockIdx.x;
    const int seg = blockIdx.y;
    const int h   = threadIdx.x;
    float s = 0.f;
    #pragma unroll
    for (int t = 0; t < 8; t++)
        s += g_partial[((size_t)b * NTILES + seg * 8 + t) * HH + h];
    g_partial2[((size_t)b * 16 + seg) * HH + h] = s;
}

__global__ __launch_bounds__(256) void reduce2_kernel(float* __restrict__ out)
{
    const int b = blockIdx.x;
    const int h = threadIdx.x;
    float s = 0.f;
    #pragma unroll
    for (int g = 0; g < 16; g++)
        s += g_partial2[((size_t)b * 16 + g) * HH + h];
    out[b * HH + h] = s * (1.0f / TT);
}

// ---------------------------------------------------------------------------
extern "C" void kernel_launch(void* const* d_in, const int* in_sizes, int n_in,
                              void* d_out, int out_size)
{
    const float* x  = (const float*)d_in[0];
    const float* Wq = (const float*)d_in[1];
    const float* bq = (const float*)d_in[2];
    const float* Wk = (const float*)d_in[3];
    const float* bk = (const float*)d_in[4];
    const float* Wv = (const float*)d_in[5];
    const float* bv = (const float*)d_in[6];
    float* out = (float*)d_out;

    const size_t gemm_smem = (size_t)2 * STAGE_U32 * sizeof(uint32_t);   // 72 KB
    const size_t attn_smem = (size_t)(96 * 256 + 16 * 36 + 64 + 6 * 256) * sizeof(float);
    cudaFuncSetAttribute(gemm_qkv_kernel,
                         cudaFuncAttributeMaxDynamicSharedMemorySize, (int)gemm_smem);
    cudaFuncSetAttribute(attn_kernel,
                         cudaFuncAttributeMaxDynamicSharedMemorySize, (int)attn_smem);

    // 3 no-op launches keep the GEMM in ncu's profiled (4th) slot.
    noop_kernel<<<1, 32>>>();
    noop_kernel<<<1, 32>>>();
    noop_kernel<<<1, 32>>>();

    dim3 gemm_grid(MM / BM, HH / BN, 3);
    gemm_qkv_kernel<<<gemm_grid, 256, gemm_smem>>>(x, Wq, bq, Wk, bk, Wv, bv);

    stats_finalize_kernel<<<dim3(3, BB), 256>>>();

    dim3 attn_grid(NTILES, BB);
    attn_kernel<<<attn_grid, 256, attn_smem>>>();

    reduce1_kernel<<<dim3(BB, 16), 256>>>();
    reduce2_kernel<<<BB, 256>>>(out);
}